// round 9
// baseline (speedup 1.0000x reference)
#include <cuda_runtime.h>
#include <math.h>
#include <stdint.h>

#define Dm 1024
#define Fm 4096
#define Em 8
#define Tm 4096
#define TK (Tm*2)

// ---------------- scratch (static device globals) ----------------
__device__ int   g_count[Em];
__device__ int   g_entries[Em*Tm];       // per-expert list: token index
__device__ int   g_slot[TK];             // token,k -> e*Tm+pos
__device__ float g_topw[TK];
__device__ float g_Xr[(size_t)Tm*Dm];            // tf32-pre-rounded x
__device__ float g_W1r[(size_t)Em*Fm*Dm];        // tf32-pre-rounded W1 (134 MB)
__device__ float g_W2r[(size_t)Em*Dm*Fm];        // tf32-pre-rounded W2 (134 MB)
__device__ float g_H[(size_t)Em*Tm*Fm];          // [e][pos][F] (tf32-rounded)
__device__ float g_Y[(size_t)Em*Tm*Dm];          // [e][pos][D]

// ---------------- PTX helpers (base sm_90 ISA only) ----------------
__device__ __forceinline__ uint32_t s2u(const void* p) {
    uint32_t a;
    asm("{ .reg .u64 t; cvta.to.shared.u64 t, %1; cvt.u32.u64 %0, t; }" : "=r"(a) : "l"(p));
    return a;
}

__device__ __forceinline__ uint32_t f2tf(float f) {
    uint32_t u;
    asm("cvt.rna.tf32.f32 %0, %1;" : "=r"(u) : "f"(f));
    return u;
}

__device__ __forceinline__ void mma_tf32(float* d, const uint32_t* a, const uint32_t* b) {
    asm volatile(
        "mma.sync.aligned.m16n8k8.row.col.f32.tf32.tf32.f32 "
        "{%0,%1,%2,%3}, {%4,%5,%6,%7}, {%8,%9}, {%0,%1,%2,%3};"
        : "+f"(d[0]), "+f"(d[1]), "+f"(d[2]), "+f"(d[3])
        : "r"(a[0]), "r"(a[1]), "r"(a[2]), "r"(a[3]), "r"(b[0]), "r"(b[1]));
}

#define BULK128(dst, src, mbar) \
    asm volatile("cp.async.bulk.shared::cluster.global.mbarrier::complete_tx::bytes [%0], [%1], %2, [%3];" \
        :: "r"(dst), "l"(src), "r"(128), "r"(mbar) : "memory")

#define MBAR_INIT(mbar, cnt) \
    asm volatile("mbarrier.init.shared.b64 [%0], %1;" :: "r"(mbar), "r"((uint32_t)(cnt)) : "memory")
#define MBAR_EXPECT_TX(mbar, bytes) \
    asm volatile("mbarrier.arrive.expect_tx.shared.b64 _, [%0], %1;" :: "r"(mbar), "r"((uint32_t)(bytes)) : "memory")

#define WAIT_PARITY(mbar, ph) do {                                               \
    uint32_t _m = (mbar), _p = (uint32_t)(ph), _d;                               \
    asm volatile(                                                                \
        "{\n\t.reg .pred p;\n\t"                                                 \
        "mbarrier.try_wait.parity.acquire.cta.shared::cta.b64 p, [%1], %2;\n\t"  \
        "selp.b32 %0, 1, 0, p;\n\t}"                                             \
        : "=r"(_d) : "r"(_m), "r"(_p) : "memory");                               \
    if (!_d) {                                                                   \
        asm volatile(                                                            \
            "{\n\t.reg .pred P1;\n\t"                                            \
            "W_%=:\n\t"                                                          \
            "mbarrier.try_wait.parity.acquire.cta.shared::cta.b64 P1, [%0], %1, 0x989680;\n\t" \
            "@P1 bra.uni D_%=;\n\t"                                              \
            "bra.uni W_%=;\n\t"                                                  \
            "D_%=:\n\t}"                                                         \
            :: "r"(_m), "r"(_p) : "memory");                                     \
    }                                                                            \
} while (0)

// ---------------- weight pre-round (tf32 rna) ----------------
__global__ void preround_kernel(const float* __restrict__ src, float* __restrict__ dst) {
    size_t i = ((size_t)blockIdx.x * blockDim.x + threadIdx.x) * 4;
    float4 v = *(const float4*)(src + i);
    v.x = __uint_as_float(f2tf(v.x));
    v.y = __uint_as_float(f2tf(v.y));
    v.z = __uint_as_float(f2tf(v.z));
    v.w = __uint_as_float(f2tf(v.w));
    *(float4*)(dst + i) = v;
}

// ---------------- router ----------------
__global__ void zero_counts_kernel() {
    if (threadIdx.x < Em) g_count[threadIdx.x] = 0;
}

__global__ void router_kernel(const float* __restrict__ x,
                              const float* __restrict__ Wr) {
    int w    = (blockIdx.x * blockDim.x + threadIdx.x) >> 5;
    int lane = threadIdx.x & 31;
    if (w >= Tm) return;
    const float* xr = x + (size_t)w * Dm;
    float* xo = g_Xr + (size_t)w * Dm;
    float acc[Em];
#pragma unroll
    for (int e = 0; e < Em; e++) acc[e] = 0.f;
    for (int j = lane; j < Dm; j += 32) {
        float xv = xr[j];
        xo[j] = __uint_as_float(f2tf(xv));
#pragma unroll
        for (int e = 0; e < Em; e++) acc[e] = fmaf(xv, Wr[e*Dm + j], acc[e]);
    }
#pragma unroll
    for (int e = 0; e < Em; e++) {
#pragma unroll
        for (int off = 16; off; off >>= 1)
            acc[e] += __shfl_xor_sync(0xffffffffu, acc[e], off);
    }
    if (lane == 0) {
        int e0 = 0; float v0 = acc[0];
#pragma unroll
        for (int e = 1; e < Em; e++) if (acc[e] > v0) { v0 = acc[e]; e0 = e; }
        int e1 = -1; float v1 = -1e30f;
#pragma unroll
        for (int e = 0; e < Em; e++) if (e != e0 && acc[e] > v1) { v1 = acc[e]; e1 = e; }
        float b  = expf(v1 - v0);
        g_topw[w*2 + 0] = 1.f / (1.f + b);
        g_topw[w*2 + 1] = b  / (1.f + b);
        int p0 = atomicAdd(&g_count[e0], 1);
        g_entries[e0*Tm + p0] = w;
        g_slot[w*2 + 0] = e0*Tm + p0;
        int p1 = atomicAdd(&g_count[e1], 1);
        g_entries[e1*Tm + p1] = w;
        g_slot[w*2 + 1] = e1*Tm + p1;
    }
}

// ---------------- tf32 mma.sync GEMM, bulk-fed, fully cvt-free mainloop ----
// block tile 128(M) x 128(N), K-chunk 32, 2-stage mbarrier pipeline.
// 8 warps @ 64x32. smem pitch 48 floats (192B rows) -> conflict-free LDS.128.
#define PITCH 48
#define AROWS 128
#define BROWS 128
#define A_BYTES (AROWS*PITCH*4)                     // 24576
#define STG_BYTES ((AROWS+BROWS)*PITCH*4)           // 49152
#define NSTG 2
#define SMEM_DYN (NSTG*STG_BYTES)                   // 98304  -> 2 CTAs/SM
#define TX_BYTES ((AROWS+BROWS)*128)                // 32768

template<int KTOT, int ASTRIDE, bool GATHER, int BSTRIDE, int NTOT, bool GELU>
__global__ __launch_bounds__(256, 2)
void moe_gemm(const float* __restrict__ W,
              const float* __restrict__ bias)
{
    int e    = blockIdx.z;
    int cnt  = g_count[e];
    int row0 = blockIdx.y * 128;
    if (row0 >= cnt) return;
    int col0 = blockIdx.x * 128;

    extern __shared__ __align__(16) char dsm[];
    __shared__ __align__(8) uint64_t sMbar[NSTG];

    int tid  = threadIdx.x;
    int lane = tid & 31;
    int w    = tid >> 5;

    float* Out = GELU ? g_H : g_Y;

    uint32_t sbase = s2u(dsm);
    uint32_t mb0 = s2u(&sMbar[0]);
    uint32_t mb1 = s2u(&sMbar[1]);

    if (tid == 0) { MBAR_INIT(mb0, 1); MBAR_INIT(mb1, 1); }
    __syncthreads();

    // per-thread bulk source row: tid<128 -> A row tid; else B row tid-128
    const float* src;
    uint32_t dst;
    if (tid < AROWS) {
        if (GATHER) {
            int i   = row0 + tid;
            int tok = g_entries[e*Tm + ((i < cnt) ? i : 0)];
            src = g_Xr + (size_t)tok*ASTRIDE;
        } else {
            src = g_H + (size_t)(e*Tm + row0 + tid)*ASTRIDE;
        }
        dst = sbase + tid*(PITCH*4);
    } else {
        src = W + (size_t)e*Fm*Dm + (size_t)(col0 + tid - AROWS)*BSTRIDE;
        dst = sbase + A_BYTES + (tid - AROWS)*(PITCH*4);
    }

    constexpr int NCH = KTOT / 32;

    auto loadChunk = [&](int c, int stg) {
        if (tid == 0) MBAR_EXPECT_TX(stg ? mb1 : mb0, TX_BYTES);
        BULK128(dst + stg*STG_BYTES, src + (size_t)c*32, stg ? mb1 : mb0);
    };

    loadChunk(0, 0);
    loadChunk(1, 1);

    float acc[4][4][4];
#pragma unroll
    for (int i = 0; i < 4; i++)
#pragma unroll
        for (int j = 0; j < 4; j++)
#pragma unroll
            for (int q = 0; q < 4; q++) acc[i][j][q] = 0.f;

    int wm = w & 1, wn = w >> 1;    // warp tile rows wm*64..+63, cols wn*32..+31
    int qr = lane >> 2;
    int qc = lane & 3;

    int ph0 = 0, ph1 = 0;

    for (int c = 0; c < NCH; c++) {
        int stg = c & 1;
        // leader waits on TMA completion; everyone else parks at the barrier
        if (tid == 0) {
            if (stg == 0) { WAIT_PARITY(mb0, ph0); ph0 ^= 1; }
            else          { WAIT_PARITY(mb1, ph1); ph1 ^= 1; }
        }
        __syncthreads();

        const float* As = (const float*)(dsm + stg*STG_BYTES);
        const float* Bs = (const float*)(dsm + stg*STG_BYTES + A_BYTES);

#pragma unroll
        for (int p = 0; p < 2; p++) {
            int kb = p*16 + 4*qc;
            float4 alo[4], ahi[4];
            uint32_t bF[4][4];
#pragma unroll
            for (int mt = 0; mt < 4; mt++) {
                int r = wm*64 + mt*16 + qr;
                alo[mt] = *(const float4*)(As + r*PITCH + kb);
                ahi[mt] = *(const float4*)(As + (r+8)*PITCH + kb);
            }
#pragma unroll
            for (int nt = 0; nt < 4; nt++) {
                int n = wn*32 + nt*8 + qr;
                float4 bv = *(const float4*)(Bs + n*PITCH + kb);
                bF[nt][0] = __float_as_uint(bv.x); bF[nt][1] = __float_as_uint(bv.y);
                bF[nt][2] = __float_as_uint(bv.z); bF[nt][3] = __float_as_uint(bv.w);
            }
            {
                uint32_t aF[4];
#pragma unroll
                for (int mt = 0; mt < 4; mt++) {
                    aF[0] = __float_as_uint(alo[mt].x);
                    aF[1] = __float_as_uint(ahi[mt].x);
                    aF[2] = __float_as_uint(alo[mt].y);
                    aF[3] = __float_as_uint(ahi[mt].y);
#pragma unroll
                    for (int nt = 0; nt < 4; nt++)
                        mma_tf32(acc[mt][nt], aF, &bF[nt][0]);
                }
#pragma unroll
                for (int mt = 0; mt < 4; mt++) {
                    aF[0] = __float_as_uint(alo[mt].z);
                    aF[1] = __float_as_uint(ahi[mt].z);
                    aF[2] = __float_as_uint(alo[mt].w);
                    aF[3] = __float_as_uint(ahi[mt].w);
#pragma unroll
                    for (int nt = 0; nt < 4; nt++)
                        mma_tf32(acc[mt][nt], aF, &bF[nt][2]);
                }
            }
        }
        __syncthreads();                 // all warps done reading this stage
        if (c + NSTG < NCH) loadChunk(c + NSTG, stg);
    }

    // ---- epilogue: bias + (gelu, tf32-round) + contiguous row stores ----
    const float* bia = bias + e*NTOT + col0;
#pragma unroll
    for (int mt = 0; mt < 4; mt++) {
        int r0 = wm*64 + mt*16 + qr;
        float* o0 = Out + (size_t)(e*Tm + row0 + r0)*NTOT + col0;
        float* o1 = Out + (size_t)(e*Tm + row0 + r0 + 8)*NTOT + col0;
#pragma unroll
        for (int nt = 0; nt < 4; nt++) {
            int cc = wn*32 + nt*8 + 2*qc;
            float bv0 = bia[cc], bv1 = bia[cc + 1];
            float t0 = acc[mt][nt][0] + bv0;
            float t1 = acc[mt][nt][1] + bv1;
            float t2 = acc[mt][nt][2] + bv0;
            float t3 = acc[mt][nt][3] + bv1;
            if (GELU) {
                t0 = 0.5f*t0*(1.f + erff(t0*0.70710678118654752f));
                t1 = 0.5f*t1*(1.f + erff(t1*0.70710678118654752f));
                t2 = 0.5f*t2*(1.f + erff(t2*0.70710678118654752f));
                t3 = 0.5f*t3*(1.f + erff(t3*0.70710678118654752f));
                t0 = __uint_as_float(f2tf(t0));
                t1 = __uint_as_float(f2tf(t1));
                t2 = __uint_as_float(f2tf(t2));
                t3 = __uint_as_float(f2tf(t3));
            }
            *(float2*)(o0 + cc) = make_float2(t0, t1);
            *(float2*)(o1 + cc) = make_float2(t2, t3);
        }
    }
}

// ---------------- combine ----------------
__global__ void combine_kernel(float* __restrict__ out) {
    int idx = blockIdx.x * blockDim.x + threadIdx.x;  // float4 index
    if (idx >= Tm*Dm/4) return;
    int t  = idx / (Dm/4);
    int d4 = idx % (Dm/4);
    float w0 = g_topw[t*2 + 0];
    float w1 = g_topw[t*2 + 1];
    int s0 = g_slot[t*2 + 0];
    int s1 = g_slot[t*2 + 1];
    const float4 y0 = *(const float4*)&g_Y[(size_t)s0*Dm + d4*4];
    const float4 y1 = *(const float4*)&g_Y[(size_t)s1*Dm + d4*4];
    float4 o;
    o.x = w0*y0.x + w1*y1.x;
    o.y = w0*y0.y + w1*y1.y;
    o.z = w0*y0.z + w1*y1.z;
    o.w = w0*y0.w + w1*y1.w;
    *(float4*)&out[(size_t)idx*4] = o;
}

// ---------------- launch ----------------
extern "C" void kernel_launch(void* const* d_in, const int* in_sizes, int n_in,
                              void* d_out, int out_size) {
    const float* x  = (const float*)d_in[0];
    const float* Wr = (const float*)d_in[1];
    const float* W1 = (const float*)d_in[2];
    const float* b1 = (const float*)d_in[3];
    const float* W2 = (const float*)d_in[4];
    const float* b2 = (const float*)d_in[5];
    float* out = (float*)d_out;

    auto k1 = moe_gemm<Dm, Dm, true,  Dm, Fm, true>;   // H = gelu(Xr @ W1r^T + b1)
    auto k2 = moe_gemm<Fm, Fm, false, Fm, Dm, false>;  // Y = H @ W2r^T + b2
    static bool attr_done = false;
    if (!attr_done) {
        cudaFuncSetAttribute(k1, cudaFuncAttributeMaxDynamicSharedMemorySize, SMEM_DYN);
        cudaFuncSetAttribute(k2, cudaFuncAttributeMaxDynamicSharedMemorySize, SMEM_DYN);
        attr_done = true;
    }

    // resolve device-global addresses for preround targets
    float *w1r_p, *w2r_p;
    cudaGetSymbolAddress((void**)&w1r_p, g_W1r);
    cudaGetSymbolAddress((void**)&w2r_p, g_W2r);

    zero_counts_kernel<<<1, 32>>>();
    router_kernel<<<(Tm*32 + 255)/256, 256>>>(x, Wr);

    // pre-round weights to tf32 (rna) — removes all in-loop CVTs
    const size_t nW = (size_t)Em*Fm*Dm;            // 33.55M floats
    preround_kernel<<<(unsigned)(nW/4/256), 256>>>(W1, w1r_p);
    preround_kernel<<<(unsigned)(nW/4/256), 256>>>(W2, w2r_p);

    dim3 g1(Fm/128, Tm/128, Em);   // (32, 32, 8)
    k1<<<g1, 256, SMEM_DYN>>>(w1r_p, b1);

    dim3 g2(Dm/128, Tm/128, Em);   // (8, 32, 8)
    k2<<<g2, 256, SMEM_DYN>>>(w2r_p, b2);

    combine_kernel<<<(Tm*Dm/4 + 255)/256, 256>>>(out);
}

// round 10
// speedup vs baseline: 1.7725x; 1.7725x over previous
#include <cuda_runtime.h>
#include <cuda_fp16.h>
#include <math.h>
#include <stdint.h>

#define Dm 1024
#define Fm 4096
#define Em 8
#define Tm 4096
#define TK (Tm*2)

// ---------------- scratch (static device globals) ----------------
__device__ int    g_count[Em];
__device__ int    g_entries[Em*Tm];      // per-expert list: token index
__device__ int    g_slot[TK];            // token,k -> e*Tm+pos
__device__ float  g_topw[TK];
__device__ __half g_Xh[(size_t)Tm*Dm];           // fp16, k-permuted (8 MB)
__device__ __half g_W1h[(size_t)Em*Fm*Dm];       // fp16, k-permuted (67 MB)
__device__ __half g_W2h[(size_t)Em*Dm*Fm];       // fp16, k-permuted (67 MB)
__device__ __half g_H[(size_t)Em*Tm*Fm];         // [e][pos][F] fp16 k-permuted (268 MB)
__device__ float  g_Y[(size_t)Em*Tm*Dm];         // [e][pos][D] fp32 (134 MB)

// k-permutation within each 64-element block: places each mma thread's
// fragment halves contiguously (16B per thread per 2 k-steps).
__device__ __forceinline__ int kperm(int kk) {
    int s   = kk >> 4;            // k-step 0..3
    int sig = kk & 15;            // slot within k-step
    int qc  = (sig & 7) >> 1;     // owning thread column
    int v   = (sig & 1) | ((sig & 8) >> 2);
    return ((s >> 1) << 5) + (qc << 3) + ((s & 1) << 2) + v;
}

// ---------------- PTX helpers (base sm_90 ISA only) ----------------
__device__ __forceinline__ uint32_t s2u(const void* p) {
    uint32_t a;
    asm("{ .reg .u64 t; cvta.to.shared.u64 t, %1; cvt.u32.u64 %0, t; }" : "=r"(a) : "l"(p));
    return a;
}

__device__ __forceinline__ void mma_f16(float* d,
                                        uint32_t a0, uint32_t a1, uint32_t a2, uint32_t a3,
                                        uint32_t b0, uint32_t b1) {
    asm volatile(
        "mma.sync.aligned.m16n8k16.row.col.f32.f16.f16.f32 "
        "{%0,%1,%2,%3}, {%4,%5,%6,%7}, {%8,%9}, {%0,%1,%2,%3};"
        : "+f"(d[0]), "+f"(d[1]), "+f"(d[2]), "+f"(d[3])
        : "r"(a0), "r"(a1), "r"(a2), "r"(a3), "r"(b0), "r"(b1));
}

#define BULK128(dst, src, mbar) \
    asm volatile("cp.async.bulk.shared::cluster.global.mbarrier::complete_tx::bytes [%0], [%1], %2, [%3];" \
        :: "r"(dst), "l"(src), "r"(128), "r"(mbar) : "memory")

#define MBAR_INIT(mbar, cnt) \
    asm volatile("mbarrier.init.shared.b64 [%0], %1;" :: "r"(mbar), "r"((uint32_t)(cnt)) : "memory")
#define MBAR_EXPECT_TX(mbar, bytes) \
    asm volatile("mbarrier.arrive.expect_tx.shared.b64 _, [%0], %1;" :: "r"(mbar), "r"((uint32_t)(bytes)) : "memory")

#define WAIT_PARITY(mbar, ph) do {                                               \
    uint32_t _m = (mbar), _p = (uint32_t)(ph), _d;                               \
    asm volatile(                                                                \
        "{\n\t.reg .pred p;\n\t"                                                 \
        "mbarrier.try_wait.parity.acquire.cta.shared::cta.b64 p, [%1], %2;\n\t"  \
        "selp.b32 %0, 1, 0, p;\n\t}"                                             \
        : "=r"(_d) : "r"(_m), "r"(_p) : "memory");                               \
    if (!_d) {                                                                   \
        asm volatile(                                                            \
            "{\n\t.reg .pred P1;\n\t"                                            \
            "W_%=:\n\t"                                                          \
            "mbarrier.try_wait.parity.acquire.cta.shared::cta.b64 P1, [%0], %1, 0x989680;\n\t" \
            "@P1 bra.uni D_%=;\n\t"                                              \
            "bra.uni W_%=;\n\t"                                                  \
            "D_%=:\n\t}"                                                         \
            :: "r"(_m), "r"(_p) : "memory");                                     \
    }                                                                            \
} while (0)

// ---------------- weight convert: fp32 -> fp16 with k-permutation ----------
__global__ void convw_kernel(const float* __restrict__ src, __half* __restrict__ dst) {
    size_t i4   = (size_t)blockIdx.x * blockDim.x + threadIdx.x;
    size_t base = i4 * 4;                       // 4 consecutive k, 4-aligned
    float4 v = *(const float4*)(src + base);
    int kk = (int)(base & 63);                  // aligned to 4
    int s = kk >> 4, sig = kk & 15;
    int qc = (sig & 7) >> 1;
    int vv = (sig & 8) >> 2;                    // sig&1 == 0 here
    int h  = ((s >> 1) << 5) + (qc << 3) + ((s & 1) << 2) + vv;
    size_t out = base & ~(size_t)63;
    *(__half2*)(dst + out + h)     = __floats2half2_rn(v.x, v.y);
    *(__half2*)(dst + out + h + 8) = __floats2half2_rn(v.z, v.w);
}

// ---------------- router (also writes fp16 k-permuted x copy) -------------
__global__ void zero_counts_kernel() {
    if (threadIdx.x < Em) g_count[threadIdx.x] = 0;
}

__global__ void router_kernel(const float* __restrict__ x,
                              const float* __restrict__ Wr) {
    int w    = (blockIdx.x * blockDim.x + threadIdx.x) >> 5;
    int lane = threadIdx.x & 31;
    if (w >= Tm) return;
    const float* xr = x + (size_t)w * Dm;
    __half* xo = g_Xh + (size_t)w * Dm;
    float acc[Em];
#pragma unroll
    for (int e = 0; e < Em; e++) acc[e] = 0.f;
    for (int j = lane; j < Dm; j += 32) {
        float xv = xr[j];
        xo[(j & ~63) + kperm(j & 63)] = __float2half_rn(xv);
#pragma unroll
        for (int e = 0; e < Em; e++) acc[e] = fmaf(xv, Wr[e*Dm + j], acc[e]);
    }
#pragma unroll
    for (int e = 0; e < Em; e++) {
#pragma unroll
        for (int off = 16; off; off >>= 1)
            acc[e] += __shfl_xor_sync(0xffffffffu, acc[e], off);
    }
    if (lane == 0) {
        int e0 = 0; float v0 = acc[0];
#pragma unroll
        for (int e = 1; e < Em; e++) if (acc[e] > v0) { v0 = acc[e]; e0 = e; }
        int e1 = -1; float v1 = -1e30f;
#pragma unroll
        for (int e = 0; e < Em; e++) if (e != e0 && acc[e] > v1) { v1 = acc[e]; e1 = e; }
        float b  = expf(v1 - v0);
        g_topw[w*2 + 0] = 1.f / (1.f + b);
        g_topw[w*2 + 1] = b  / (1.f + b);
        int p0 = atomicAdd(&g_count[e0], 1);
        g_entries[e0*Tm + p0] = w;
        g_slot[w*2 + 0] = e0*Tm + p0;
        int p1 = atomicAdd(&g_count[e1], 1);
        g_entries[e1*Tm + p1] = w;
        g_slot[w*2 + 1] = e1*Tm + p1;
    }
}

// ---------------- fp16 m16n8k16 GEMM, bulk-fed, single-sync loop ----------
// block tile 128(M) x 128(N), K-chunk 64 (fp16 = 128B/row), 2-stage.
// 8 warps @ 64x32. pitch 192B (=64 mod 128 -> conflict-free LDS.128).
#define PITCHB 192
#define AROWS 128
#define BROWS 128
#define A_BYTES (AROWS*PITCHB)                      // 24576
#define STG_BYTES ((AROWS+BROWS)*PITCHB)            // 49152
#define NSTG 2
#define SMEM_DYN (NSTG*STG_BYTES)                   // 98304  -> 2 CTAs/SM
#define TX_BYTES ((AROWS+BROWS)*128)                // 32768

template<int KTOT, int ASTRIDE, bool GATHER, int BSTRIDE, int NTOT, bool GELU>
__global__ __launch_bounds__(256, 2)
void moe_gemm(const __half* __restrict__ W,
              const float* __restrict__ bias)
{
    int e    = blockIdx.z;
    int cnt  = g_count[e];
    int row0 = blockIdx.y * 128;
    if (row0 >= cnt) return;
    int col0 = blockIdx.x * 128;

    extern __shared__ __align__(16) char dsm[];
    __shared__ __align__(8) uint64_t sMbar[NSTG];

    int tid  = threadIdx.x;
    int lane = tid & 31;
    int w    = tid >> 5;

    uint32_t sbase = s2u(dsm);
    uint32_t mb0 = s2u(&sMbar[0]);
    uint32_t mb1 = s2u(&sMbar[1]);

    if (tid == 0) { MBAR_INIT(mb0, 1); MBAR_INIT(mb1, 1); }
    __syncthreads();

    // per-thread bulk source row: tid<128 -> A row tid; else B row tid-128
    const __half* src;
    uint32_t dst;
    if (tid < AROWS) {
        if (GATHER) {
            int i   = row0 + tid;
            int tok = g_entries[e*Tm + ((i < cnt) ? i : 0)];
            src = g_Xh + (size_t)tok*ASTRIDE;
        } else {
            src = g_H + (size_t)(e*Tm + row0 + tid)*ASTRIDE;
        }
        dst = sbase + tid*PITCHB;
    } else {
        src = W + (size_t)e*Fm*Dm + (size_t)(col0 + tid - AROWS)*BSTRIDE;
        dst = sbase + A_BYTES + (tid - AROWS)*PITCHB;
    }

    constexpr int NCH = KTOT / 64;

    auto loadChunk = [&](int c, int stg) {
        if (tid == 0) MBAR_EXPECT_TX(stg ? mb1 : mb0, TX_BYTES);
        BULK128(dst + stg*STG_BYTES, src + (size_t)c*64, stg ? mb1 : mb0);
    };

    loadChunk(0, 0);

    float acc[4][4][4];
#pragma unroll
    for (int i = 0; i < 4; i++)
#pragma unroll
        for (int j = 0; j < 4; j++)
#pragma unroll
            for (int q = 0; q < 4; q++) acc[i][j][q] = 0.f;

    int wm = w & 1, wn = w >> 1;    // warp tile rows wm*64..+63, cols wn*32..+31
    int qr = lane >> 2;
    int qc = lane & 3;

    int ph0 = 0, ph1 = 0;

    for (int c = 0; c < NCH; c++) {
        int stg = c & 1;
        // leader waits for this stage's data; barrier doubles as
        // "all warps finished the other stage" for the next load.
        if (tid == 0) {
            if (stg == 0) { WAIT_PARITY(mb0, ph0); ph0 ^= 1; }
            else          { WAIT_PARITY(mb1, ph1); ph1 ^= 1; }
        }
        __syncthreads();
        if (c + 1 < NCH) loadChunk(c + 1, stg ^ 1);

        const char* As = dsm + stg*STG_BYTES;
        const char* Bs = As + A_BYTES;

#pragma unroll
        for (int half = 0; half < 2; half++) {
            int ofs = half*64 + qc*16;
            uint4 Alo[4], Ahi[4], Bv[4];
#pragma unroll
            for (int mt = 0; mt < 4; mt++) {
                int r = wm*64 + mt*16 + qr;
                Alo[mt] = *(const uint4*)(As + r*PITCHB + ofs);
                Ahi[mt] = *(const uint4*)(As + (r+8)*PITCHB + ofs);
            }
#pragma unroll
            for (int nt = 0; nt < 4; nt++) {
                int n = wn*32 + nt*8 + qr;
                Bv[nt] = *(const uint4*)(Bs + n*PITCHB + ofs);
            }
#pragma unroll
            for (int s = 0; s < 2; s++) {
#pragma unroll
                for (int mt = 0; mt < 4; mt++) {
                    const uint32_t* al = (const uint32_t*)&Alo[mt];
                    const uint32_t* ah = (const uint32_t*)&Ahi[mt];
#pragma unroll
                    for (int nt = 0; nt < 4; nt++) {
                        const uint32_t* bb = (const uint32_t*)&Bv[nt];
                        mma_f16(acc[mt][nt],
                                al[2*s], ah[2*s], al[2*s+1], ah[2*s+1],
                                bb[2*s], bb[2*s+1]);
                    }
                }
            }
        }
    }

    // ---- epilogue ----
    const float* bia = bias + e*NTOT + col0;
#pragma unroll
    for (int mt = 0; mt < 4; mt++) {
        int r0 = wm*64 + mt*16 + qr;
#pragma unroll
        for (int nt = 0; nt < 4; nt++) {
            int cc = wn*32 + nt*8 + 2*qc;
            float bv0 = bia[cc], bv1 = bia[cc + 1];
            float t0 = acc[mt][nt][0] + bv0;
            float t1 = acc[mt][nt][1] + bv1;
            float t2 = acc[mt][nt][2] + bv0;
            float t3 = acc[mt][nt][3] + bv1;
            if (GELU) {
                // gelu then store H as fp16, k-permuted (it feeds gemm2's A)
                t0 = 0.5f*t0*(1.f + erff(t0*0.70710678118654752f));
                t1 = 0.5f*t1*(1.f + erff(t1*0.70710678118654752f));
                t2 = 0.5f*t2*(1.f + erff(t2*0.70710678118654752f));
                t3 = 0.5f*t3*(1.f + erff(t3*0.70710678118654752f));
                int po = (cc & ~63) + kperm(cc & 63);       // even pair
                __half* h0 = g_H + (size_t)(e*Tm + row0 + r0)*NTOT + col0 + po;
                __half* h1 = g_H + (size_t)(e*Tm + row0 + r0 + 8)*NTOT + col0 + po;
                *(__half2*)h0 = __floats2half2_rn(t0, t1);
                *(__half2*)h1 = __floats2half2_rn(t2, t3);
            } else {
                float* o0 = g_Y + (size_t)(e*Tm + row0 + r0)*NTOT + col0;
                float* o1 = g_Y + (size_t)(e*Tm + row0 + r0 + 8)*NTOT + col0;
                *(float2*)(o0 + cc) = make_float2(t0, t1);
                *(float2*)(o1 + cc) = make_float2(t2, t3);
            }
        }
    }
}

// ---------------- combine ----------------
__global__ void combine_kernel(float* __restrict__ out) {
    int idx = blockIdx.x * blockDim.x + threadIdx.x;  // float4 index
    if (idx >= Tm*Dm/4) return;
    int t  = idx / (Dm/4);
    int d4 = idx % (Dm/4);
    float w0 = g_topw[t*2 + 0];
    float w1 = g_topw[t*2 + 1];
    int s0 = g_slot[t*2 + 0];
    int s1 = g_slot[t*2 + 1];
    const float4 y0 = *(const float4*)&g_Y[(size_t)s0*Dm + d4*4];
    const float4 y1 = *(const float4*)&g_Y[(size_t)s1*Dm + d4*4];
    float4 o;
    o.x = w0*y0.x + w1*y1.x;
    o.y = w0*y0.y + w1*y1.y;
    o.z = w0*y0.z + w1*y1.z;
    o.w = w0*y0.w + w1*y1.w;
    *(float4*)&out[(size_t)idx*4] = o;
}

// ---------------- launch ----------------
extern "C" void kernel_launch(void* const* d_in, const int* in_sizes, int n_in,
                              void* d_out, int out_size) {
    const float* x  = (const float*)d_in[0];
    const float* Wr = (const float*)d_in[1];
    const float* W1 = (const float*)d_in[2];
    const float* b1 = (const float*)d_in[3];
    const float* W2 = (const float*)d_in[4];
    const float* b2 = (const float*)d_in[5];
    float* out = (float*)d_out;

    auto k1 = moe_gemm<Dm, Dm, true,  Dm, Fm, true>;   // H = gelu(Xh @ W1h^T + b1)
    auto k2 = moe_gemm<Fm, Fm, false, Fm, Dm, false>;  // Y = H @ W2h^T + b2
    static bool attr_done = false;
    if (!attr_done) {
        cudaFuncSetAttribute(k1, cudaFuncAttributeMaxDynamicSharedMemorySize, SMEM_DYN);
        cudaFuncSetAttribute(k2, cudaFuncAttributeMaxDynamicSharedMemorySize, SMEM_DYN);
        attr_done = true;
    }

    __half *w1h_p, *w2h_p;
    cudaGetSymbolAddress((void**)&w1h_p, g_W1h);
    cudaGetSymbolAddress((void**)&w2h_p, g_W2h);

    zero_counts_kernel<<<1, 32>>>();
    router_kernel<<<(Tm*32 + 255)/256, 256>>>(x, Wr);

    // convert weights to fp16, k-permuted
    const size_t nW = (size_t)Em*Fm*Dm;            // 33.55M elements
    convw_kernel<<<(unsigned)(nW/4/256), 256>>>(W1, w1h_p);
    convw_kernel<<<(unsigned)(nW/4/256), 256>>>(W2, w2h_p);

    dim3 g1(Fm/128, Tm/128, Em);   // (32, 32, 8)
    k1<<<g1, 256, SMEM_DYN>>>(w1h_p, b1);

    dim3 g2(Dm/128, Tm/128, Em);   // (8, 32, 8)
    k2<<<g2, 256, SMEM_DYN>>>(w2h_p, b2);

    combine_kernel<<<(Tm*Dm/4 + 255)/256, 256>>>(out);
}

// round 12
// speedup vs baseline: 1.8116x; 1.0221x over previous
#include <cuda_runtime.h>
#include <cuda_fp16.h>
#include <math.h>
#include <stdint.h>

#define Dm 1024
#define Fm 4096
#define Em 8
#define Tm 4096
#define TK (Tm*2)

// ---------------- scratch (static device globals) ----------------
__device__ int    g_count[Em];
__device__ int    g_entries[Em*Tm];      // per-expert list: token index
__device__ int    g_slot[TK];            // token,k -> e*Tm+pos
__device__ float  g_topw[TK];
__device__ __half g_Xh[(size_t)Tm*Dm];           // fp16, k-permuted
__device__ __half g_W1h[(size_t)Em*Fm*Dm];       // fp16, k-permuted
__device__ __half g_W2h[(size_t)Em*Dm*Fm];       // fp16, k-permuted
__device__ __half g_H[(size_t)Em*Tm*Fm];         // [e][pos][F] fp16 k-permuted
__device__ float  g_Y[(size_t)Em*Tm*Dm];         // [e][pos][D] fp32

// k-permutation within each 64-element block: places each mma thread's
// fragment halves contiguously (16B per thread per 2 k-steps).
__device__ __forceinline__ int kperm(int kk) {
    int s   = kk >> 4;
    int sig = kk & 15;
    int qc  = (sig & 7) >> 1;
    int v   = (sig & 1) | ((sig & 8) >> 2);
    return ((s >> 1) << 5) + (qc << 3) + ((s & 1) << 2) + v;
}

// ---------------- PTX helpers (base sm_90 ISA only) ----------------
__device__ __forceinline__ uint32_t s2u(const void* p) {
    uint32_t a;
    asm("{ .reg .u64 t; cvta.to.shared.u64 t, %1; cvt.u32.u64 %0, t; }" : "=r"(a) : "l"(p));
    return a;
}

__device__ __forceinline__ void mma_f16(float* d,
                                        uint32_t a0, uint32_t a1, uint32_t a2, uint32_t a3,
                                        uint32_t b0, uint32_t b1) {
    asm volatile(
        "mma.sync.aligned.m16n8k16.row.col.f32.f16.f16.f32 "
        "{%0,%1,%2,%3}, {%4,%5,%6,%7}, {%8,%9}, {%0,%1,%2,%3};"
        : "+f"(d[0]), "+f"(d[1]), "+f"(d[2]), "+f"(d[3])
        : "r"(a0), "r"(a1), "r"(a2), "r"(a3), "r"(b0), "r"(b1));
}

#define BULK128(dst, src, mbar) \
    asm volatile("cp.async.bulk.shared::cluster.global.mbarrier::complete_tx::bytes [%0], [%1], %2, [%3];" \
        :: "r"(dst), "l"(src), "r"(128), "r"(mbar) : "memory")

#define MBAR_INIT(mbar, cnt) \
    asm volatile("mbarrier.init.shared.b64 [%0], %1;" :: "r"(mbar), "r"((uint32_t)(cnt)) : "memory")
#define MBAR_EXPECT_TX(mbar, bytes) \
    asm volatile("mbarrier.arrive.expect_tx.shared.b64 _, [%0], %1;" :: "r"(mbar), "r"((uint32_t)(bytes)) : "memory")

#define WAIT_PARITY(mbar, ph) do {                                               \
    uint32_t _m = (mbar), _p = (uint32_t)(ph), _d;                               \
    asm volatile(                                                                \
        "{\n\t.reg .pred p;\n\t"                                                 \
        "mbarrier.try_wait.parity.acquire.cta.shared::cta.b64 p, [%1], %2;\n\t"  \
        "selp.b32 %0, 1, 0, p;\n\t}"                                             \
        : "=r"(_d) : "r"(_m), "r"(_p) : "memory");                               \
    if (!_d) {                                                                   \
        asm volatile(                                                            \
            "{\n\t.reg .pred P1;\n\t"                                            \
            "W_%=:\n\t"                                                          \
            "mbarrier.try_wait.parity.acquire.cta.shared::cta.b64 P1, [%0], %1, 0x989680;\n\t" \
            "@P1 bra.uni D_%=;\n\t"                                              \
            "bra.uni W_%=;\n\t"                                                  \
            "D_%=:\n\t}"                                                         \
            :: "r"(_m), "r"(_p) : "memory");                                     \
    }                                                                            \
} while (0)

// ---------------- weight convert (both weights, one launch) ---------------
__global__ void convw_kernel(const float* __restrict__ W1, const float* __restrict__ W2,
                             __half* __restrict__ D1, __half* __restrict__ D2,
                             size_t n4) {
    size_t i4 = (size_t)blockIdx.x * blockDim.x + threadIdx.x;
    const float* src;
    __half* dst;
    size_t base;
    if (i4 < n4) { src = W1; dst = D1; base = i4 * 4; }
    else         { src = W2; dst = D2; base = (i4 - n4) * 4; }
    float4 v = *(const float4*)(src + base);
    int kk = (int)(base & 63);
    int s = kk >> 4, sig = kk & 15;
    int qc = (sig & 7) >> 1;
    int vv = (sig & 8) >> 2;
    int h  = ((s >> 1) << 5) + (qc << 3) + ((s & 1) << 2) + vv;
    size_t out = base & ~(size_t)63;
    *(__half2*)(dst + out + h)     = __floats2half2_rn(v.x, v.y);
    *(__half2*)(dst + out + h + 8) = __floats2half2_rn(v.z, v.w);
}

// ---------------- router ----------------
__global__ void zero_counts_kernel() {
    if (threadIdx.x < Em) g_count[threadIdx.x] = 0;
}

__global__ void router_kernel(const float* __restrict__ x,
                              const float* __restrict__ Wr) {
    int w    = (blockIdx.x * blockDim.x + threadIdx.x) >> 5;
    int lane = threadIdx.x & 31;
    if (w >= Tm) return;
    const float* xr = x + (size_t)w * Dm;
    __half* xo = g_Xh + (size_t)w * Dm;
    float acc[Em];
#pragma unroll
    for (int e = 0; e < Em; e++) acc[e] = 0.f;
    for (int j = lane; j < Dm; j += 32) {
        float xv = xr[j];
        xo[(j & ~63) + kperm(j & 63)] = __float2half_rn(xv);
#pragma unroll
        for (int e = 0; e < Em; e++) acc[e] = fmaf(xv, Wr[e*Dm + j], acc[e]);
    }
#pragma unroll
    for (int e = 0; e < Em; e++) {
#pragma unroll
        for (int off = 16; off; off >>= 1)
            acc[e] += __shfl_xor_sync(0xffffffffu, acc[e], off);
    }
    if (lane == 0) {
        int e0 = 0; float v0 = acc[0];
#pragma unroll
        for (int e = 1; e < Em; e++) if (acc[e] > v0) { v0 = acc[e]; e0 = e; }
        int e1 = -1; float v1 = -1e30f;
#pragma unroll
        for (int e = 0; e < Em; e++) if (e != e0 && acc[e] > v1) { v1 = acc[e]; e1 = e; }
        float b  = expf(v1 - v0);
        g_topw[w*2 + 0] = 1.f / (1.f + b);
        g_topw[w*2 + 1] = b  / (1.f + b);
        int p0 = atomicAdd(&g_count[e0], 1);
        g_entries[e0*Tm + p0] = w;
        g_slot[w*2 + 0] = e0*Tm + p0;
        int p1 = atomicAdd(&g_count[e1], 1);
        g_entries[e1*Tm + p1] = w;
        g_slot[w*2 + 1] = e1*Tm + p1;
    }
}

// ---------------- fp16 m16n8k16 GEMM, bulk-fed, distributed wait ----------
// block tile 128(M) x 128(N), K-chunk 64 (fp16 = 128B/row), 2-stage.
// 8 warps @ 64x32. pitch 192B (only all-distinct-bank pitch) -> LDS.128 cf.
#define PITCHB 192
#define AROWS 128
#define BROWS 128
#define A_BYTES (AROWS*PITCHB)                      // 24576
#define STG_BYTES ((AROWS+BROWS)*PITCHB)            // 49152
#define NSTG 2
#define SMEM_DYN (NSTG*STG_BYTES)                   // 98304  -> 2 CTAs/SM
#define TX_BYTES ((AROWS+BROWS)*128)                // 32768

template<int KTOT, int ASTRIDE, bool GATHER, int BSTRIDE, int NTOT, bool GELU>
__global__ __launch_bounds__(256, 2)
void moe_gemm(const __half* __restrict__ W,
              const float* __restrict__ bias)
{
    int e    = blockIdx.z;
    int cnt  = g_count[e];
    int row0 = blockIdx.y * 128;
    if (row0 >= cnt) return;
    int col0 = blockIdx.x * 128;

    extern __shared__ __align__(16) char dsm[];
    __shared__ __align__(8) uint64_t sMbar[NSTG];

    int tid  = threadIdx.x;
    int lane = tid & 31;
    int w    = tid >> 5;

    uint32_t sbase = s2u(dsm);
    uint32_t mb0 = s2u(&sMbar[0]);
    uint32_t mb1 = s2u(&sMbar[1]);

    if (tid == 0) { MBAR_INIT(mb0, 1); MBAR_INIT(mb1, 1); }
    __syncthreads();

    // per-thread bulk source row: tid<128 -> A row tid; else B row tid-128
    const __half* src;
    uint32_t dst;
    if (tid < AROWS) {
        if (GATHER) {
            int i   = row0 + tid;
            int tok = g_entries[e*Tm + ((i < cnt) ? i : 0)];
            src = g_Xh + (size_t)tok*ASTRIDE;
        } else {
            src = g_H + (size_t)(e*Tm + row0 + tid)*ASTRIDE;
        }
        dst = sbase + tid*PITCHB;
    } else {
        src = W + (size_t)e*Fm*Dm + (size_t)(col0 + tid - AROWS)*BSTRIDE;
        dst = sbase + A_BYTES + (tid - AROWS)*PITCHB;
    }

    constexpr int NCH = KTOT / 64;

    auto loadChunk = [&](int c, int stg) {
        if (tid == 0) MBAR_EXPECT_TX(stg ? mb1 : mb0, TX_BYTES);
        BULK128(dst + stg*STG_BYTES, src + (size_t)c*64, stg ? mb1 : mb0);
    };

    loadChunk(0, 0);
    loadChunk(1, 1);

    float acc[4][4][4];
#pragma unroll
    for (int i = 0; i < 4; i++)
#pragma unroll
        for (int j = 0; j < 4; j++)
#pragma unroll
            for (int q = 0; q < 4; q++) acc[i][j][q] = 0.f;

    int wm = w & 1, wn = w >> 1;    // warp tile rows wm*64..+63, cols wn*32..+31
    int qr = lane >> 2;
    int qc = lane & 3;

    for (int c = 0; c < NCH; c++) {
        int stg = c & 1;
        int par = (c >> 1) & 1;     // phase of this stage's mbarrier use
        // DISTRIBUTED wait: every warp sleeps on the full barrier directly
        // and starts its fragment loads the moment the TMA lands.
        WAIT_PARITY(stg ? mb1 : mb0, par);

        const char* As = dsm + stg*STG_BYTES;
        const char* Bs = As + A_BYTES;

#pragma unroll
        for (int half = 0; half < 2; half++) {
            int ofs = half*64 + qc*16;
            uint4 Alo[4], Ahi[4], Bv[4];
#pragma unroll
            for (int mt = 0; mt < 4; mt++) {
                int r = wm*64 + mt*16 + qr;
                Alo[mt] = *(const uint4*)(As + r*PITCHB + ofs);
                Ahi[mt] = *(const uint4*)(As + (r+8)*PITCHB + ofs);
            }
#pragma unroll
            for (int nt = 0; nt < 4; nt++) {
                int n = wn*32 + nt*8 + qr;
                Bv[nt] = *(const uint4*)(Bs + n*PITCHB + ofs);
            }
#pragma unroll
            for (int s = 0; s < 2; s++) {
#pragma unroll
                for (int mt = 0; mt < 4; mt++) {
                    const uint32_t* al = (const uint32_t*)&Alo[mt];
                    const uint32_t* ah = (const uint32_t*)&Ahi[mt];
#pragma unroll
                    for (int nt = 0; nt < 4; nt++) {
                        const uint32_t* bb = (const uint32_t*)&Bv[nt];
                        mma_f16(acc[mt][nt],
                                al[2*s], ah[2*s], al[2*s+1], ah[2*s+1],
                                bb[2*s], bb[2*s+1]);
                    }
                }
            }
        }
        // consumed-fence: all warps done reading stage stg
        __syncthreads();
        if (c + NSTG < NCH) loadChunk(c + NSTG, stg);
    }

    // ---- epilogue ----
    const float* bia = bias + e*NTOT + col0;
#pragma unroll
    for (int mt = 0; mt < 4; mt++) {
        int r0 = wm*64 + mt*16 + qr;
#pragma unroll
        for (int nt = 0; nt < 4; nt++) {
            int cc = wn*32 + nt*8 + 2*qc;
            float bv0 = bia[cc], bv1 = bia[cc + 1];
            float t0 = acc[mt][nt][0] + bv0;
            float t1 = acc[mt][nt][1] + bv1;
            float t2 = acc[mt][nt][2] + bv0;
            float t3 = acc[mt][nt][3] + bv1;
            if (GELU) {
                t0 = 0.5f*t0*(1.f + erff(t0*0.70710678118654752f));
                t1 = 0.5f*t1*(1.f + erff(t1*0.70710678118654752f));
                t2 = 0.5f*t2*(1.f + erff(t2*0.70710678118654752f));
                t3 = 0.5f*t3*(1.f + erff(t3*0.70710678118654752f));
                int po = (cc & ~63) + kperm(cc & 63);       // even pair
                __half* h0 = g_H + (size_t)(e*Tm + row0 + r0)*NTOT + col0 + po;
                __half* h1 = g_H + (size_t)(e*Tm + row0 + r0 + 8)*NTOT + col0 + po;
                *(__half2*)h0 = __floats2half2_rn(t0, t1);
                *(__half2*)h1 = __floats2half2_rn(t2, t3);
            } else {
                float* o0 = g_Y + (size_t)(e*Tm + row0 + r0)*NTOT + col0;
                float* o1 = g_Y + (size_t)(e*Tm + row0 + r0 + 8)*NTOT + col0;
                *(float2*)(o0 + cc) = make_float2(t0, t1);
                *(float2*)(o1 + cc) = make_float2(t2, t3);
            }
        }
    }
}

// ---------------- combine ----------------
__global__ void combine_kernel(float* __restrict__ out) {
    int idx = blockIdx.x * blockDim.x + threadIdx.x;  // float4 index
    if (idx >= Tm*Dm/4) return;
    int t  = idx / (Dm/4);
    int d4 = idx % (Dm/4);
    float w0 = g_topw[t*2 + 0];
    float w1 = g_topw[t*2 + 1];
    int s0 = g_slot[t*2 + 0];
    int s1 = g_slot[t*2 + 1];
    const float4 y0 = *(const float4*)&g_Y[(size_t)s0*Dm + d4*4];
    const float4 y1 = *(const float4*)&g_Y[(size_t)s1*Dm + d4*4];
    float4 o;
    o.x = w0*y0.x + w1*y1.x;
    o.y = w0*y0.y + w1*y1.y;
    o.z = w0*y0.z + w1*y1.z;
    o.w = w0*y0.w + w1*y1.w;
    *(float4*)&out[(size_t)idx*4] = o;
}

// ---------------- launch ----------------
extern "C" void kernel_launch(void* const* d_in, const int* in_sizes, int n_in,
                              void* d_out, int out_size) {
    const float* x  = (const float*)d_in[0];
    const float* Wr = (const float*)d_in[1];
    const float* W1 = (const float*)d_in[2];
    const float* b1 = (const float*)d_in[3];
    const float* W2 = (const float*)d_in[4];
    const float* b2 = (const float*)d_in[5];
    float* out = (float*)d_out;

    auto k1 = moe_gemm<Dm, Dm, true,  Dm, Fm, true>;   // H = gelu(Xh @ W1h^T + b1)
    auto k2 = moe_gemm<Fm, Fm, false, Fm, Dm, false>;  // Y = H @ W2h^T + b2
    static bool attr_done = false;
    if (!attr_done) {
        cudaFuncSetAttribute(k1, cudaFuncAttributeMaxDynamicSharedMemorySize, SMEM_DYN);
        cudaFuncSetAttribute(k2, cudaFuncAttributeMaxDynamicSharedMemorySize, SMEM_DYN);
        attr_done = true;
    }

    __half *w1h_p, *w2h_p;
    cudaGetSymbolAddress((void**)&w1h_p, g_W1h);
    cudaGetSymbolAddress((void**)&w2h_p, g_W2h);

    zero_counts_kernel<<<1, 32>>>();
    router_kernel<<<(Tm*32 + 255)/256, 256>>>(x, Wr);

    // convert both weight tensors to fp16 (k-permuted) in one launch
    const size_t n4 = (size_t)Em*Fm*Dm/4;          // 8.39M float4 per tensor
    convw_kernel<<<(unsigned)(2*n4/256), 256>>>(W1, W2, w1h_p, w2h_p, n4);

    dim3 g1(Fm/128, Tm/128, Em);   // (32, 32, 8)
    k1<<<g1, 256, SMEM_DYN>>>(w1h_p, b1);

    dim3 g2(Dm/128, Tm/128, Em);   // (8, 32, 8)
    k2<<<g2, 256, SMEM_DYN>>>(w2h_p, b2);

    combine_kernel<<<(Tm*Dm/4 + 255)/256, 256>>>(out);
}